// round 12
// baseline (speedup 1.0000x reference)
#include <cuda_runtime.h>
#include <cstdint>
#include <cmath>

#define GH 512
#define GK 50
#define KPAD 52
#define GT 1024
#define GB 128
#define GM (GB * GT)
#define BPP 52
#define RPC 886            // rows per persistent gemm CTA (148*886 >= 131072)

// Scratch for projected features [B*T, K]
__device__ float g_feats[(size_t)GM * GK + 64];

// Packed fp32x2 ops (sm_103a)
#define FFMA2(acc, x, w) \
    asm("fma.rn.f32x2 %0, %1, %2, %0;" : "+l"(acc) : "l"(x), "l"(w))
#define FADD2(res, a, b) \
    asm("add.rn.f32x2 %0, %1, %2;" : "=l"(res) : "l"(a), "l"(b))

// ---------------------------------------------------------------------------
// Kernel 1: persistent GEMM, grid = 148 (one CTA per SM, no wave quantization).
// Each CTA owns 886 rows, processed in 256-row chunks (1 row/thread).
// Inner loop = round-1 proven pattern (serial k, f32x2 FFMA, Wt broadcast
// LDS) so per-row summation order is unchanged -> rel_err stays 0.
// Partial chunk: whole warps with no active row skip the k-loop entirely.
// ---------------------------------------------------------------------------
__global__ __launch_bounds__(256, 1) void gemm_kernel(
    const float* __restrict__ hidden, const float* __restrict__ W,
    const float* __restrict__ bias) {
    extern __shared__ float Wt[];  // [GH][KPAD]
    const int tid = threadIdx.x;

    for (int idx = tid; idx < GK * GH; idx += 256) {
        int k = idx >> 9;
        int h = idx & 511;
        Wt[h * KPAD + k] = W[idx];
    }
    __syncthreads();

    const int start = blockIdx.x * RPC;
    const int end   = (start + RPC < GM) ? (start + RPC) : GM;

    for (int row0 = start; row0 < end; row0 += 256) {
        const int row = row0 + tid;
        if (row < end) {
            const float4* hx = reinterpret_cast<const float4*>(
                hidden + (size_t)row * GH);

            unsigned long long acc[25];
#pragma unroll
            for (int q = 0; q < 25; q++) acc[q] = 0ull;

            float4 a0 = hx[0], a1 = hx[1];
            for (int hc = 0; hc < 64; hc++) {
                float xs[8] = {a0.x, a0.y, a0.z, a0.w, a1.x, a1.y, a1.z, a1.w};
                if (hc < 63) { a0 = hx[2 * hc + 2]; a1 = hx[2 * hc + 3]; }
#pragma unroll
                for (int u = 0; u < 8; u++) {
                    const int h = hc * 8 + u;
                    unsigned long long X;
                    asm("mov.b64 %0, {%1, %1};" : "=l"(X) : "r"(__float_as_uint(xs[u])));
                    const float* wr = Wt + h * KPAD;
#pragma unroll
                    for (int q = 0; q < 12; q++) {
                        ulonglong2 w = *reinterpret_cast<const ulonglong2*>(wr + q * 4);
                        FFMA2(acc[2 * q],     X, w.x);
                        FFMA2(acc[2 * q + 1], X, w.y);
                    }
                    unsigned long long wl =
                        *reinterpret_cast<const unsigned long long*>(wr + 48);
                    FFMA2(acc[24], X, wl);
                }
            }

            float2* o = reinterpret_cast<float2*>(g_feats + (size_t)row * GK);
            const float2* bb = reinterpret_cast<const float2*>(bias);
#pragma unroll
            for (int q = 0; q < 25; q++) {
                float2 bv = bb[q];
                float2 v = *reinterpret_cast<float2*>(&acc[q]);
                v.x += bv.x; v.y += bv.y;
                o[q] = v;
            }
        }
    }
}

// ---------------------------------------------------------------------------
// Pairwise argmax tree with COMPILE-TIME ids: adjacent pairs keep index-
// ordered subranges, so strict '>' == jnp.argmax first-max tie-breaking.
// ---------------------------------------------------------------------------
template <int Wd>
__device__ __forceinline__ void argmax_tree(float* val, int* id) {
    if constexpr (Wd > 1) {
        constexpr int P = Wd >> 1;
#pragma unroll
        for (int m = 0; m < P; m++) {
            bool g = val[2 * m + 1] > val[2 * m];
            val[m] = g ? val[2 * m + 1] : val[2 * m];
            id[m]  = g ? id[2 * m + 1]  : id[2 * m];
        }
        if constexpr (Wd & 1) { val[P] = val[Wd - 1]; id[P] = id[Wd - 1]; }
        argmax_tree<((Wd + 1) >> 1)>(val, id);
    }
}

// ---------------------------------------------------------------------------
// Kernel 2: Viterbi, 224 threads / 7 warps (proven sweet spot). Thread (j,r):
// j = tid>>2 in [0,56), r = tid&3, slice of 14 states at i0 = 14r (even ->
// aligned LDS.64; pads -inf). Candidate adds: 7 packed FADD2. Tree ids are
// compile-time. Epilogue split: r==0 does v-store + feats ring, r==2 stores
// bp. Backpointers in smem -> backtrace is an LDS pointer chase.
// ---------------------------------------------------------------------------
__global__ __launch_bounds__(224, 1) void viterbi_kernel(
    const float* __restrict__ trans, const float* __restrict__ startt,
    const float* __restrict__ stopt, float* __restrict__ out) {
    extern __shared__ char smv[];
    unsigned char* bp = reinterpret_cast<unsigned char*>(smv);        // 1023*52
    float* vbuf = reinterpret_cast<float*>(smv + 53200);              // [2][64]
    float* red  = vbuf + 128;                                         // [64]
    unsigned char* tags = reinterpret_cast<unsigned char*>(red + 64); // [1024]

    const int b = blockIdx.x;
    const int tid = threadIdx.x;
    const int j = tid >> 2;        // 0..55 (j >= 50 pad)
    const int r = tid & 3;
    const int i0 = r * 14;         // 0,14,28,42
    const float* F = g_feats + (size_t)b * GT * GK;
    const bool act = (j < GK);

    // Packed transition slice: trp[p] = (tr[i0+2p], tr[i0+2p+1]), -inf pads
    unsigned long long trp[7];
#pragma unroll
    for (int p = 0; p < 7; p++) {
        int ia = i0 + 2 * p, ib = ia + 1;
        float ta = (act && ia < GK) ? trans[ia * GK + j] : -INFINITY;
        float tb = (act && ib < GK) ? trans[ib * GK + j] : -INFINITY;
        asm("mov.b64 %0, {%1, %2};" : "=l"(trp[p])
            : "r"(__float_as_uint(ta)), "r"(__float_as_uint(tb)));
    }

    // Pads: slots [50,64) of both vbuf halves to -inf
    if (tid >= GK && tid < 64) { vbuf[tid] = -INFINITY; vbuf[64 + tid] = -INFINITY; }
    if (r == 0 && act) vbuf[j] = F[j] + startt[j];

    // Feats prefetch ring, depth 4 (owned by r==0 lanes)
    float fr[4];
    if (r == 0 && act) {
#pragma unroll
        for (int u = 0; u < 4; u++) fr[u] = F[(1 + u) * GK + j];
    }
    __syncthreads();

    for (int t = 1; t < GT; t += 4) {
#pragma unroll
        for (int u = 0; u < 4; u++) {
            const int tt = t + u;
            if (tt < GT) {  // uniform across block: barrier inside is legal
                const float* vr = vbuf + (((tt - 1) & 1) << 6) + i0;
                float cand[14];
                int id[14];
#pragma unroll
                for (int p = 0; p < 7; p++) {
                    unsigned long long x =
                        *reinterpret_cast<const unsigned long long*>(vr + 2 * p);
                    unsigned long long res;
                    FADD2(res, x, trp[p]);
                    float2 rf = *reinterpret_cast<float2*>(&res);
                    cand[2 * p]     = rf.x;
                    cand[2 * p + 1] = rf.y;
                    id[2 * p]     = 2 * p;       // compile-time constants
                    id[2 * p + 1] = 2 * p + 1;
                }
                argmax_tree<14>(cand, id);
                float best = cand[0];
                int bi = i0 + id[0];

                // Merge 4 partials across r (lower global index wins ties)
                float ov = __shfl_xor_sync(0xffffffffu, best, 1);
                int   oi = __shfl_xor_sync(0xffffffffu, bi, 1);
                bool g1 = (ov > best) || (ov == best && oi < bi);
                best = g1 ? ov : best;
                bi   = g1 ? oi : bi;
                ov = __shfl_xor_sync(0xffffffffu, best, 2);
                oi = __shfl_xor_sync(0xffffffffu, bi, 2);
                bool g2 = (ov > best) || (ov == best && oi < bi);
                best = g2 ? ov : best;
                bi   = g2 ? oi : bi;

                // Split epilogue: r==0 stores v + rotates feats ring,
                // r==2 stores the backpointer (bi identical in all lanes).
                if (r == 0 && act) {
                    vbuf[((tt & 1) << 6) + j] = fr[u] + best;
                    int tn = tt + 4;
                    if (tn > GT - 1) tn = GT - 1;
                    fr[u] = F[tn * GK + j];
                } else if (r == 2 && act) {
                    bp[(tt - 1) * BPP + j] = (unsigned char)bi;
                }
                __syncthreads();
            }
        }
    }

    // Final: v at t=1023 lives in buffer half 1
    if (r == 0 && act) red[j] = vbuf[64 + j] + stopt[j];
    __syncthreads();

    if (tid == 0) {
        float best = -INFINITY;
        int bj = 0;
        for (int k = 0; k < GK; k++) {
            float s = red[k];
            if (s > best) { best = s; bj = k; }
        }
        out[b] = best;
        int tag = bj;
        tags[GT - 1] = (unsigned char)tag;
        for (int k = GT - 2; k >= 0; k--) {
            tag = bp[k * BPP + tag];
            tags[k] = (unsigned char)tag;
        }
    }
    __syncthreads();

    // Parallel coalesced tag writeout
    float* tout = out + GB + (size_t)b * GT;
    for (int k = tid; k < GT; k += 224) tout[k] = (float)tags[k];
}

extern "C" void kernel_launch(void* const* d_in, const int* in_sizes, int n_in,
                              void* d_out, int out_size) {
    const float* hidden = (const float*)d_in[0];
    const float* W      = (const float*)d_in[1];
    const float* bias   = (const float*)d_in[2];
    const float* trans  = (const float*)d_in[3];
    const float* startt = (const float*)d_in[4];
    const float* stopt  = (const float*)d_in[5];
    float* out = (float*)d_out;

    const size_t wsm = (size_t)GH * KPAD * sizeof(float);          // 106,496 B
    cudaFuncSetAttribute(gemm_kernel, cudaFuncAttributeMaxDynamicSharedMemorySize, (int)wsm);
    gemm_kernel<<<148, 256, wsm>>>(hidden, W, bias);

    const size_t vsm = 53200 + (128 + 64) * sizeof(float) + 1024;  // 54,992 B
    cudaFuncSetAttribute(viterbi_kernel, cudaFuncAttributeMaxDynamicSharedMemorySize, (int)vsm);
    viterbi_kernel<<<GB, 224, vsm>>>(trans, startt, stopt, out);
}

// round 13
// speedup vs baseline: 1.8030x; 1.8030x over previous
#include <cuda_runtime.h>
#include <cstdint>
#include <cmath>

#define GH 512
#define GK 50
#define KPAD 52
#define GT 1024
#define GB 128
#define GM (GB * GT)
#define BPP 52

// Scratch for projected features [B*T, K]
__device__ float g_feats[(size_t)GM * GK + 64];

// Packed fp32x2 FMA (sm_103a): acc = x * w + acc
#define FFMA2(acc, x, w) \
    asm("fma.rn.f32x2 %0, %1, %2, %0;" : "+l"(acc) : "l"(x), "l"(w))

// ---------------------------------------------------------------------------
// Kernel 1 (round-1/round-4 proven, 212-213us measured twice):
// feats = hidden @ W^T + b. 256 CTAs x 256 threads, 2 rows/thread.
// W transposed in smem [h][52], broadcast LDS.128 conflict-free; all math
// packed f32x2 FFMA; software-pipelined row loads.
// ---------------------------------------------------------------------------
__global__ __launch_bounds__(256, 1) void gemm_kernel(
    const float* __restrict__ hidden, const float* __restrict__ W,
    const float* __restrict__ bias) {
    extern __shared__ float Wt[];  // [GH][KPAD]
    const int tid = threadIdx.x;

    for (int idx = tid; idx < GK * GH; idx += 256) {
        int k = idx >> 9;
        int h = idx & 511;
        Wt[h * KPAD + k] = W[idx];
    }
    __syncthreads();

    const size_t base = (size_t)blockIdx.x * 512;
    const float4* r0 = reinterpret_cast<const float4*>(hidden + (base + tid) * GH);
    const float4* r1 = reinterpret_cast<const float4*>(hidden + (base + tid + 256) * GH);

    unsigned long long acc0[25], acc1[25];
#pragma unroll
    for (int q = 0; q < 25; q++) { acc0[q] = 0ull; acc1[q] = 0ull; }

    float4 a0 = r0[0], a1 = r0[1];
    float4 b0 = r1[0], b1 = r1[1];

    for (int hc = 0; hc < 64; hc++) {
        float xs0[8] = {a0.x, a0.y, a0.z, a0.w, a1.x, a1.y, a1.z, a1.w};
        float xs1[8] = {b0.x, b0.y, b0.z, b0.w, b1.x, b1.y, b1.z, b1.w};
        if (hc < 63) {
            a0 = r0[2 * hc + 2]; a1 = r0[2 * hc + 3];
            b0 = r1[2 * hc + 2]; b1 = r1[2 * hc + 3];
        }
#pragma unroll
        for (int u = 0; u < 8; u++) {
            const int h = hc * 8 + u;
            unsigned long long X0, X1;
            asm("mov.b64 %0, {%1, %1};" : "=l"(X0) : "r"(__float_as_uint(xs0[u])));
            asm("mov.b64 %0, {%1, %1};" : "=l"(X1) : "r"(__float_as_uint(xs1[u])));
            const float* wr = Wt + h * KPAD;
#pragma unroll
            for (int q = 0; q < 12; q++) {
                ulonglong2 w = *reinterpret_cast<const ulonglong2*>(wr + q * 4);
                FFMA2(acc0[2 * q],     X0, w.x);
                FFMA2(acc0[2 * q + 1], X0, w.y);
                FFMA2(acc1[2 * q],     X1, w.x);
                FFMA2(acc1[2 * q + 1], X1, w.y);
            }
            unsigned long long wl = *reinterpret_cast<const unsigned long long*>(wr + 48);
            FFMA2(acc0[24], X0, wl);
            FFMA2(acc1[24], X1, wl);
        }
    }

    float2* o0 = reinterpret_cast<float2*>(g_feats + (base + tid) * GK);
    float2* o1 = reinterpret_cast<float2*>(g_feats + (base + tid + 256) * GK);
    const float2* bb = reinterpret_cast<const float2*>(bias);
#pragma unroll
    for (int q = 0; q < 25; q++) {
        float2 bv = bb[q];
        float2 v0 = *reinterpret_cast<float2*>(&acc0[q]);
        float2 v1 = *reinterpret_cast<float2*>(&acc1[q]);
        v0.x += bv.x; v0.y += bv.y;
        v1.x += bv.x; v1.y += bv.y;
        o0[q] = v0;
        o1[q] = v1;
    }
}

// ---------------------------------------------------------------------------
// Pairwise argmax tree (select-form). Adjacent pairs keep index-ordered
// subranges; strict '>' (right wins only if strictly greater) implements
// jnp.argmax first-max tie-breaking exactly.
// ---------------------------------------------------------------------------
template <int Wd>
__device__ __forceinline__ void argmax_tree(float* val, int* id) {
    if constexpr (Wd > 1) {
        constexpr int P = Wd >> 1;
#pragma unroll
        for (int m = 0; m < P; m++) {
            bool g = val[2 * m + 1] > val[2 * m];
            val[m] = g ? val[2 * m + 1] : val[2 * m];
            id[m]  = g ? id[2 * m + 1]  : id[2 * m];
        }
        if constexpr (Wd & 1) { val[P] = val[Wd - 1]; id[P] = id[Wd - 1]; }
        argmax_tree<((Wd + 1) >> 1)>(val, id);
    }
}

// ---------------------------------------------------------------------------
// Kernel 2 (round-3 proven, 308us measured): fused Viterbi forward +
// backtrace. One CTA (224 thr / 7 warps) per batch. Thread (j, r):
// j = tid>>2, r = tid&3, 13-wide scalar i-slices (conflict-free LDS).
// Tree argmax (depth 4) + two shfl merges. Backpointers entirely in smem ->
// backtrace is an LDS pointer chase. Parallel coalesced tag writeout.
// ---------------------------------------------------------------------------
__global__ __launch_bounds__(224, 1) void viterbi_kernel(
    const float* __restrict__ trans, const float* __restrict__ startt,
    const float* __restrict__ stopt, float* __restrict__ out) {
    extern __shared__ char smv[];
    unsigned char* bp = reinterpret_cast<unsigned char*>(smv);        // 1023*52
    float* vbuf = reinterpret_cast<float*>(smv + 53200);              // [2][64]
    float* red  = vbuf + 128;                                         // [64]
    unsigned char* tags = reinterpret_cast<unsigned char*>(red + 64); // [1024]

    const int b = blockIdx.x;
    const int tid = threadIdx.x;
    const int j = tid >> 2;
    const int r = tid & 3;
    const float* F = g_feats + (size_t)b * GT * GK;

    const int i0 = r * 13;

    float tr[13];
#pragma unroll
    for (int ii = 0; ii < 13; ii++) {
        int i = i0 + ii;
        tr[ii] = (j < GK && i < GK) ? trans[i * GK + j] : -INFINITY;
    }

    if (tid >= GK && tid < 64) { vbuf[tid] = -INFINITY; vbuf[64 + tid] = -INFINITY; }
    if (r == 0 && j < GK) vbuf[j] = F[j] + startt[j];

    float fr[4];
    if (r == 0 && j < GK) {
#pragma unroll
        for (int u = 0; u < 4; u++) fr[u] = F[(1 + u) * GK + j];
    }
    __syncthreads();

    for (int t = 1; t < GT; t += 4) {
#pragma unroll
        for (int u = 0; u < 4; u++) {
            const int tt = t + u;
            if (tt < GT) {  // uniform across block
                const float* vr = vbuf + (((tt - 1) & 1) << 6);
                float cand[13];
                int id[13];
#pragma unroll
                for (int ii = 0; ii < 13; ii++) {
                    cand[ii] = vr[i0 + ii] + tr[ii];
                    id[ii] = i0 + ii;
                }
                argmax_tree<13>(cand, id);
                float best = cand[0];
                int bi = id[0];

                float ov = __shfl_xor_sync(0xffffffffu, best, 1);
                int   oi = __shfl_xor_sync(0xffffffffu, bi, 1);
                bool g1 = (ov > best) || (ov == best && oi < bi);
                best = g1 ? ov : best;
                bi   = g1 ? oi : bi;
                ov = __shfl_xor_sync(0xffffffffu, best, 2);
                oi = __shfl_xor_sync(0xffffffffu, bi, 2);
                bool g2 = (ov > best) || (ov == best && oi < bi);
                best = g2 ? ov : best;
                bi   = g2 ? oi : bi;

                if (r == 0 && j < GK) {
                    float* vw = vbuf + ((tt & 1) << 6);
                    vw[j] = fr[u] + best;
                    bp[(tt - 1) * BPP + j] = (unsigned char)bi;
                    int tn = tt + 4;
                    if (tn > GT - 1) tn = GT - 1;
                    fr[u] = F[tn * GK + j];
                }
                __syncthreads();
            }
        }
    }

    if (r == 0 && j < GK) red[j] = vbuf[64 + j] + stopt[j];
    __syncthreads();

    if (tid == 0) {
        float best = -INFINITY;
        int bj = 0;
        for (int k = 0; k < GK; k++) {
            float s = red[k];
            if (s > best) { best = s; bj = k; }
        }
        out[b] = best;
        int tag = bj;
        tags[GT - 1] = (unsigned char)tag;
        for (int k = GT - 2; k >= 0; k--) {
            tag = bp[k * BPP + tag];
            tags[k] = (unsigned char)tag;
        }
    }
    __syncthreads();

    float* tout = out + GB + (size_t)b * GT;
    for (int k = tid; k < GT; k += 224) tout[k] = (float)tags[k];
}

extern "C" void kernel_launch(void* const* d_in, const int* in_sizes, int n_in,
                              void* d_out, int out_size) {
    const float* hidden = (const float*)d_in[0];
    const float* W      = (const float*)d_in[1];
    const float* bias   = (const float*)d_in[2];
    const float* trans  = (const float*)d_in[3];
    const float* startt = (const float*)d_in[4];
    const float* stopt  = (const float*)d_in[5];
    float* out = (float*)d_out;

    const size_t wsm = (size_t)GH * KPAD * sizeof(float);          // 106,496 B
    cudaFuncSetAttribute(gemm_kernel, cudaFuncAttributeMaxDynamicSharedMemorySize, (int)wsm);
    gemm_kernel<<<GM / 512, 256, wsm>>>(hidden, W, bias);

    const size_t vsm = 53200 + (128 + 64) * sizeof(float) + 1024;  // 54,992 B
    cudaFuncSetAttribute(viterbi_kernel, cudaFuncAttributeMaxDynamicSharedMemorySize, (int)vsm);
    viterbi_kernel<<<GB, 224, vsm>>>(trans, startt, stopt, out);
}